// round 12
// baseline (speedup 1.0000x reference)
#include <cuda_runtime.h>
#include <cstdint>

#define THRESH 0.8f
#define DECAY  0.2f

constexpr int BSZ = 256;   // batch
constexpr int CH  = 4096;  // out features
constexpr int KD  = 4096;  // in features

// Scratch: 3 planes [BSZ][CH]. Phase 0 stores raw first-half sums (p0);
// phase 1 overwrites with final y = (p0 + p1) + bias.
__device__ float g_y3[3 * BSZ * CH];

typedef unsigned long long u64;

// ---- packed f32x2 helpers (Blackwell FFMA2; lane-wise exact fp32) ----
__device__ __forceinline__ u64 pack2(float lo, float hi) {
    u64 r; asm("mov.b64 %0, {%1, %2};" : "=l"(r) : "f"(lo), "f"(hi)); return r;
}
__device__ __forceinline__ void unpack2(u64 v, float& lo, float& hi) {
    asm("mov.b64 {%0, %1}, %2;" : "=f"(lo), "=f"(hi) : "l"(v));
}
__device__ __forceinline__ u64 fma2(u64 a, u64 b, u64 c) {
    u64 d; asm("fma.rn.f32x2 %0, %1, %2, %3;" : "=l"(d) : "l"(a), "l"(b), "l"(c));
    return d;
}

// ---------------- GEMM: y[j][m][n] = sum_k x[m][k]*Wj[n][k] + bj[n] ----------
// Reference-exact order (verified rel_err==0.0): split-K=2 halves {0..2047},
// {2048..4095}; each half an ascending fused-FMA chain from zero; halves
// folded (p0+p1); bias added last. Two launches: phase 0 writes p0 to g_y3,
// phase 1 computes p1 and emits (p0+p1)+bias -- bit-identical fold order.
constexpr int BM = 128, BN = 128, BK = 16, TM = 8, TN = 8;  // 256 threads

__global__ __launch_bounds__(256, 2) void gemm3_kernel(
    int phase,
    const float* __restrict__ x,
    const float* __restrict__ W1, const float* __restrict__ b1,
    const float* __restrict__ W2, const float* __restrict__ b2,
    const float* __restrict__ W3, const float* __restrict__ b3)
{
    __shared__ float As[BK][BM];   // [k][m]
    __shared__ float Bs[BK][BN];   // [k][n]

    const int tid = threadIdx.x;
    const int bx  = blockIdx.x;    // 0 .. 95
    const int by  = blockIdx.y;    // 0 .. 1

    const int blocksPerJ = CH / BN;          // 32
    const int j  = bx / blocksPerJ;
    const int n0 = (bx % blocksPerJ) * BN;
    const int m0 = by * BM;

    const float* W    = (j == 0) ? W1 : (j == 1) ? W2 : W3;
    const float* bias = (j == 0) ? b1 : (j == 1) ? b2 : b3;

    const int tx = tid % (BN / TN);   // 16 -> n octet
    const int ty = tid / (BN / TN);   // 16 -> m octet

    // accumulators: 4 m-pairs x 8 n columns, packed (m even, m odd)
    u64 run2[TM / 2][TN];
    #pragma unroll
    for (int p = 0; p < TM / 2; p++)
        #pragma unroll
        for (int q = 0; q < TN; q++) run2[p][q] = 0ULL;

    const int kbBeg = phase * 128;     // half = 2048 k = 128 BK-blocks
    const int kbEnd = kbBeg + 128;

    for (int kb = kbBeg; kb < kbEnd; kb++) {
        const int k0 = kb * BK;
        // A tile: BM x BK = 512 float4, 2 per thread
        #pragma unroll
        for (int l = 0; l < 2; l++) {
            int li  = tid + l * 256;
            int row = li >> 2;
            int kq  = (li & 3) * 4;
            float4 v = *(const float4*)(x + (size_t)(m0 + row) * KD + k0 + kq);
            As[kq + 0][row] = v.x;
            As[kq + 1][row] = v.y;
            As[kq + 2][row] = v.z;
            As[kq + 3][row] = v.w;
        }
        // W tile: BN x BK = 512 float4, 2 per thread
        #pragma unroll
        for (int l = 0; l < 2; l++) {
            int li  = tid + l * 256;
            int row = li >> 2;
            int kq  = (li & 3) * 4;
            float4 v = *(const float4*)(W + (size_t)(n0 + row) * KD + k0 + kq);
            Bs[kq + 0][row] = v.x;
            Bs[kq + 1][row] = v.y;
            Bs[kq + 2][row] = v.z;
            Bs[kq + 3][row] = v.w;
        }
        __syncthreads();

        #pragma unroll
        for (int kk = 0; kk < BK; kk++) {
            // A pairs: 8 consecutive m -> 4 packed b64 (two LDS.128)
            ulonglong2 av01 = *(const ulonglong2*)(&As[kk][ty * TM]);
            ulonglong2 av23 = *(const ulonglong2*)(&As[kk][ty * TM + 4]);
            u64 av[4] = { av01.x, av01.y, av23.x, av23.y };
            // B: 8 consecutive n, each replicated to both lanes
            float4 bv0 = *(const float4*)(&Bs[kk][tx * TN]);
            float4 bv1 = *(const float4*)(&Bs[kk][tx * TN + 4]);
            u64 bb[8] = { pack2(bv0.x, bv0.x), pack2(bv0.y, bv0.y),
                          pack2(bv0.z, bv0.z), pack2(bv0.w, bv0.w),
                          pack2(bv1.x, bv1.x), pack2(bv1.y, bv1.y),
                          pack2(bv1.z, bv1.z), pack2(bv1.w, bv1.w) };
            #pragma unroll
            for (int p = 0; p < TM / 2; p++)
                #pragma unroll
                for (int q = 0; q < TN; q++)
                    run2[p][q] = fma2(av[p], bb[q], run2[p][q]);
        }
        __syncthreads();
    }

    float* yp = g_y3 + (size_t)j * BSZ * CH;

    if (phase == 0) {
        // stash raw p0 (no bias)
        #pragma unroll
        for (int p = 0; p < TM / 2; p++) {
            int m_lo = m0 + ty * TM + 2 * p;
            int n    = n0 + tx * TN;
            float lo[TN], hi[TN];
            #pragma unroll
            for (int q = 0; q < TN; q++) unpack2(run2[p][q], lo[q], hi[q]);
            float4* r0 = (float4*)(yp + (size_t)m_lo * CH + n);
            float4* r1 = (float4*)(yp + (size_t)(m_lo + 1) * CH + n);
            r0[0] = make_float4(lo[0], lo[1], lo[2], lo[3]);
            r0[1] = make_float4(lo[4], lo[5], lo[6], lo[7]);
            r1[0] = make_float4(hi[0], hi[1], hi[2], hi[3]);
            r1[1] = make_float4(hi[4], hi[5], hi[6], hi[7]);
        }
    } else {
        // y = (p0 + p1) + bias, separately rounded (matches reference fold)
        int nb = n0 + tx * TN;
        float4 bq0 = *(const float4*)(bias + nb);
        float4 bq1 = *(const float4*)(bias + nb + 4);
        float bl[TN] = { bq0.x, bq0.y, bq0.z, bq0.w, bq1.x, bq1.y, bq1.z, bq1.w };
        #pragma unroll
        for (int p = 0; p < TM / 2; p++) {
            int m_lo = m0 + ty * TM + 2 * p;
            float* row0 = yp + (size_t)m_lo * CH + nb;
            float* row1 = yp + (size_t)(m_lo + 1) * CH + nb;
            float4 p0a = *(const float4*)(row0);
            float4 p0b = *(const float4*)(row0 + 4);
            float4 p1a = *(const float4*)(row1);
            float4 p1b = *(const float4*)(row1 + 4);
            float s0[TN] = { p0a.x, p0a.y, p0a.z, p0a.w, p0b.x, p0b.y, p0b.z, p0b.w };
            float s1[TN] = { p1a.x, p1a.y, p1a.z, p1a.w, p1b.x, p1b.y, p1b.z, p1b.w };
            float lo[TN], hi[TN];
            #pragma unroll
            for (int q = 0; q < TN; q++) {
                float a, b;
                unpack2(run2[p][q], a, b);
                lo[q] = __fadd_rn(__fadd_rn(s0[q], a), bl[q]);
                hi[q] = __fadd_rn(__fadd_rn(s1[q], b), bl[q]);
            }
            float4* r0 = (float4*)(row0);
            float4* r1 = (float4*)(row1);
            r0[0] = make_float4(lo[0], lo[1], lo[2], lo[3]);
            r0[1] = make_float4(lo[4], lo[5], lo[6], lo[7]);
            r1[0] = make_float4(hi[0], hi[1], hi[2], hi[3]);
            r1[1] = make_float4(hi[4], hi[5], hi[6], hi[7]);
        }
    }
}

// ---------------- LIF recurrence: one thread per (b, c) neuron --------------
__global__ __launch_bounds__(256) void lif_kernel(
    const float* __restrict__ Wlif, const float* __restrict__ blif,
    const int* __restrict__ winsPtr, float* __restrict__ out)
{
    const int idx = blockIdx.x * 256 + threadIdx.x;   // = b*CH + c
    const float y0 = g_y3[idx];
    const float y1 = g_y3[BSZ * CH + idx];
    const float y2 = g_y3[2 * BSZ * CH + idx];
    const float w0 = Wlif[0], w1 = Wlif[1], w2 = Wlif[2];
    const float bl = blif[0];
    const int wins = *winsPtr;

    const int b = idx >> 12;          // /CH
    const int c = idx & (CH - 1);

    float m0 = 0.f, m1 = 0.f, m2 = 0.f, m3 = 0.f;
    float s0 = 0.f, s1 = 0.f, s2 = 0.f, s3 = 0.f;

    float* o = out + (size_t)b * wins * (CH * 4) + (size_t)c * 4;

    for (int t = 0; t < wins; t++) {
        float inner = __fadd_rn(
            __fmaf_rn(m2, w2, __fmaf_rn(m1, w1, __fmul_rn(m0, w0))), bl);
        m0 = __fadd_rn(__fmul_rn(__fmul_rn(m0, DECAY), 1.f - s0), y0);
        m1 = __fadd_rn(__fmul_rn(__fmul_rn(m1, DECAY), 1.f - s1), y1);
        m2 = __fadd_rn(__fmul_rn(__fmul_rn(m2, DECAY), 1.f - s2), y2);
        m3 = __fadd_rn(__fmul_rn(__fmul_rn(m3, DECAY), 1.f - s3), inner);
        s0 = (m0 > THRESH) ? 1.f : 0.f;
        s1 = (m1 > THRESH) ? 1.f : 0.f;
        s2 = (m2 > THRESH) ? 1.f : 0.f;
        s3 = (m3 > THRESH) ? 1.f : 0.f;
        *(float4*)(o + (size_t)t * CH * 4) = make_float4(s0, s1, s2, s3);
    }
}

// ---------------- launch ----------------------------------------------------
extern "C" void kernel_launch(void* const* d_in, const int* in_sizes, int n_in,
                              void* d_out, int out_size) {
    const float* x    = (const float*)d_in[0];
    const float* W1   = (const float*)d_in[1];
    const float* b1   = (const float*)d_in[2];
    const float* W2   = (const float*)d_in[3];
    const float* b2   = (const float*)d_in[4];
    const float* W3   = (const float*)d_in[5];
    const float* b3   = (const float*)d_in[6];
    const float* Wlif = (const float*)d_in[7];
    const float* blif = (const float*)d_in[8];
    const int*   wins = (const int*)d_in[9];

    dim3 ggrid(3 * CH / BN, BSZ / BM);   // (96, 2) = 192 CTAs per phase
    gemm3_kernel<<<ggrid, 256>>>(0, x, W1, b1, W2, b2, W3, b3);
    gemm3_kernel<<<ggrid, 256>>>(1, x, W1, b1, W2, b2, W3, b3);
    lif_kernel<<<(BSZ * CH) / 256, 256>>>(Wlif, blif, wins, (float*)d_out);
}

// round 13
// speedup vs baseline: 1.4260x; 1.4260x over previous
#include <cuda_runtime.h>
#include <cstdint>

#define THRESH 0.8f
#define DECAY  0.2f

constexpr int BSZ = 256;   // batch
constexpr int CH  = 4096;  // out features
constexpr int KD  = 4096;  // in features

// Scratch: two raw half-sums per plane. g_p[z][j][b][c], z = k-half.
// Fold (p0+p1)+bias happens in lif_kernel -- identical rounding order to the
// verified reference split-K=2 fold.
__device__ float g_p[2][3 * BSZ * CH];

typedef unsigned long long u64;

// ---- packed f32x2 helpers (Blackwell FFMA2; lane-wise exact fp32) ----
__device__ __forceinline__ u64 pack2(float lo, float hi) {
    u64 r; asm("mov.b64 %0, {%1, %2};" : "=l"(r) : "f"(lo), "f"(hi)); return r;
}
__device__ __forceinline__ void unpack2(u64 v, float& lo, float& hi) {
    asm("mov.b64 {%0, %1}, %2;" : "=f"(lo), "=f"(hi) : "l"(v));
}
__device__ __forceinline__ u64 fma2(u64 a, u64 b, u64 c) {
    u64 d; asm("fma.rn.f32x2 %0, %1, %2, %3;" : "=l"(d) : "l"(a), "l"(b), "l"(c));
    return d;
}

// ---------------- GEMM half-chains: p[z][j][m][n] = sum_{k in half z} ...
// Each half is an ascending fused-FMA chain from zero (verified reference
// order). f32x2 packs two independent m-rows per instruction.
constexpr int BM = 64, BN = 128, BK = 16, TM = 8, TN = 8;  // 128 threads

__global__ __launch_bounds__(128, 4) void gemm3_kernel(
    const float* __restrict__ x,
    const float* __restrict__ W1,
    const float* __restrict__ W2,
    const float* __restrict__ W3)
{
    __shared__ float As[BK][BM];   // [k][m]
    __shared__ float Bs[BK][BN];   // [k][n]

    const int tid = threadIdx.x;
    const int bx  = blockIdx.x;    // 0 .. 95  (j * 32 + n-tile)
    const int by  = blockIdx.y;    // 0 .. 3   (m-tile)
    const int bz  = blockIdx.z;    // 0 .. 1   (k-half)

    const int j  = bx >> 5;
    const int n0 = (bx & 31) * BN;
    const int m0 = by * BM;

    const float* W = (j == 0) ? W1 : (j == 1) ? W2 : W3;

    const int tx = tid & 15;       // 16 -> n quads
    const int ty = tid >> 4;       // 8  -> m octet

    // accumulators: 4 m-pairs x 8 n columns (two separated n-quads)
    u64 run2[TM / 2][TN];
    #pragma unroll
    for (int p = 0; p < TM / 2; p++)
        #pragma unroll
        for (int q = 0; q < TN; q++) run2[p][q] = 0ULL;

    const int kbBeg = bz * 128;    // half = 2048 k = 128 BK-blocks
    const int kbEnd = kbBeg + 128;

    for (int kb = kbBeg; kb < kbEnd; kb++) {
        const int k0 = kb * BK;
        // A tile: 64 x 16 = 256 float4, 2 per thread
        #pragma unroll
        for (int l = 0; l < 2; l++) {
            int li  = tid + l * 128;
            int row = li >> 2;               // 0..63
            int kq  = (li & 3) * 4;
            float4 v = *(const float4*)(x + (size_t)(m0 + row) * KD + k0 + kq);
            As[kq + 0][row] = v.x;
            As[kq + 1][row] = v.y;
            As[kq + 2][row] = v.z;
            As[kq + 3][row] = v.w;
        }
        // B tile: 128 x 16 = 512 float4, 4 per thread
        #pragma unroll
        for (int l = 0; l < 4; l++) {
            int li  = tid + l * 128;
            int row = li >> 2;               // 0..127
            int kq  = (li & 3) * 4;
            float4 v = *(const float4*)(W + (size_t)(n0 + row) * KD + k0 + kq);
            Bs[kq + 0][row] = v.x;
            Bs[kq + 1][row] = v.y;
            Bs[kq + 2][row] = v.z;
            Bs[kq + 3][row] = v.w;
        }
        __syncthreads();

        #pragma unroll
        for (int kk = 0; kk < BK; kk++) {
            // A: 8 consecutive m -> 4 packed b64 (two LDS.128, broadcast)
            ulonglong2 av01 = *(const ulonglong2*)(&As[kk][ty * TM]);
            ulonglong2 av23 = *(const ulonglong2*)(&As[kk][ty * TM + 4]);
            u64 av[4] = { av01.x, av01.y, av23.x, av23.y };
            // B: two conflict-free 16B-stride quads: n = tx*4.. and 64+tx*4..
            float4 bv0 = *(const float4*)(&Bs[kk][tx * 4]);
            float4 bv1 = *(const float4*)(&Bs[kk][64 + tx * 4]);
            u64 bb[8] = { pack2(bv0.x, bv0.x), pack2(bv0.y, bv0.y),
                          pack2(bv0.z, bv0.z), pack2(bv0.w, bv0.w),
                          pack2(bv1.x, bv1.x), pack2(bv1.y, bv1.y),
                          pack2(bv1.z, bv1.z), pack2(bv1.w, bv1.w) };
            #pragma unroll
            for (int p = 0; p < TM / 2; p++)
                #pragma unroll
                for (int q = 0; q < TN; q++)
                    run2[p][q] = fma2(av[p], bb[q], run2[p][q]);
        }
        __syncthreads();
    }

    // store raw half-sums
    float* yp = g_p[bz] + (size_t)j * BSZ * CH;
    #pragma unroll
    for (int p = 0; p < TM / 2; p++) {
        int m_lo = m0 + ty * TM + 2 * p;
        float lo[TN], hi[TN];
        #pragma unroll
        for (int q = 0; q < TN; q++) unpack2(run2[p][q], lo[q], hi[q]);
        float* r0 = yp + (size_t)m_lo * CH + n0;
        float* r1 = yp + (size_t)(m_lo + 1) * CH + n0;
        *(float4*)(r0 + tx * 4)      = make_float4(lo[0], lo[1], lo[2], lo[3]);
        *(float4*)(r0 + 64 + tx * 4) = make_float4(lo[4], lo[5], lo[6], lo[7]);
        *(float4*)(r1 + tx * 4)      = make_float4(hi[0], hi[1], hi[2], hi[3]);
        *(float4*)(r1 + 64 + tx * 4) = make_float4(hi[4], hi[5], hi[6], hi[7]);
    }
}

// ---------------- LIF recurrence + split-K fold: one thread per (b,c) -------
__global__ __launch_bounds__(256) void lif_kernel(
    const float* __restrict__ b1, const float* __restrict__ b2,
    const float* __restrict__ b3,
    const float* __restrict__ Wlif, const float* __restrict__ blif,
    const int* __restrict__ winsPtr, float* __restrict__ out)
{
    const int idx = blockIdx.x * 256 + threadIdx.x;   // = b*CH + c
    const int b = idx >> 12;          // /CH
    const int c = idx & (CH - 1);

    // fold: y = (p0 + p1) + bias, separately rounded (reference order)
    const float y0 = __fadd_rn(__fadd_rn(g_p[0][idx],
                                         g_p[1][idx]), b1[c]);
    const float y1 = __fadd_rn(__fadd_rn(g_p[0][BSZ * CH + idx],
                                         g_p[1][BSZ * CH + idx]), b2[c]);
    const float y2 = __fadd_rn(__fadd_rn(g_p[0][2 * BSZ * CH + idx],
                                         g_p[1][2 * BSZ * CH + idx]), b3[c]);

    const float w0 = Wlif[0], w1 = Wlif[1], w2 = Wlif[2];
    const float bl = blif[0];
    const int wins = *winsPtr;

    float m0 = 0.f, m1 = 0.f, m2 = 0.f, m3 = 0.f;
    float s0 = 0.f, s1 = 0.f, s2 = 0.f, s3 = 0.f;

    float* o = out + (size_t)b * wins * (CH * 4) + (size_t)c * 4;

    for (int t = 0; t < wins; t++) {
        float inner = __fadd_rn(
            __fmaf_rn(m2, w2, __fmaf_rn(m1, w1, __fmul_rn(m0, w0))), bl);
        m0 = __fadd_rn(__fmul_rn(__fmul_rn(m0, DECAY), 1.f - s0), y0);
        m1 = __fadd_rn(__fmul_rn(__fmul_rn(m1, DECAY), 1.f - s1), y1);
        m2 = __fadd_rn(__fmul_rn(__fmul_rn(m2, DECAY), 1.f - s2), y2);
        m3 = __fadd_rn(__fmul_rn(__fmul_rn(m3, DECAY), 1.f - s3), inner);
        s0 = (m0 > THRESH) ? 1.f : 0.f;
        s1 = (m1 > THRESH) ? 1.f : 0.f;
        s2 = (m2 > THRESH) ? 1.f : 0.f;
        s3 = (m3 > THRESH) ? 1.f : 0.f;
        *(float4*)(o + (size_t)t * CH * 4) = make_float4(s0, s1, s2, s3);
    }
}

// ---------------- launch ----------------------------------------------------
extern "C" void kernel_launch(void* const* d_in, const int* in_sizes, int n_in,
                              void* d_out, int out_size) {
    const float* x    = (const float*)d_in[0];
    const float* W1   = (const float*)d_in[1];
    const float* b1   = (const float*)d_in[2];
    const float* W2   = (const float*)d_in[3];
    const float* b2   = (const float*)d_in[4];
    const float* W3   = (const float*)d_in[5];
    const float* b3   = (const float*)d_in[6];
    const float* Wlif = (const float*)d_in[7];
    const float* blif = (const float*)d_in[8];
    const int*   wins = (const int*)d_in[9];

    dim3 ggrid(96, 4, 2);   // 768 CTAs, 128 threads each
    gemm3_kernel<<<ggrid, 128>>>(x, W1, W2, W3);
    lif_kernel<<<(BSZ * CH) / 256, 256>>>(b1, b2, b3, Wlif, blif, wins,
                                          (float*)d_out);
}